// round 10
// baseline (speedup 1.0000x reference)
#include <cuda_runtime.h>
#include <cuda_fp16.h>
#include <math.h>

#define B_    8
#define N_    2048
#define FIN_  128
#define FOUT_ 64
#define BN_   (B_ * N_)

#define TI      128
#define TJ      64
#define JSPLIT  2
#define JCHUNK  (N_ / JSPLIT)
#define NT_     (JCHUNK / TJ)          // 16 tiles per block

// ---- k2 smem (fp16 tiles, pitch 72 halves = 144 B -> 16B-aligned rows,
//      row stride = 36 banks = 4 bank-quads mod 32 -> conflict-free ldmatrix)
#define HPH     72
#define HBUFH   (TJ * HPH)             // 4608 halves / buffer
#define PBUFH   (TI * HPH)             // 9216 halves / buffer
#define OFF_PB  (2 * HBUFH)
#define SM_S1_BYTE ((2 * HBUFH + 2 * PBUFH) * 2)   // 55296
#define SM2_BYTES  (SM_S1_BYTE + 3 * 128 * 4)      // 56832

// ---- k1 smem (proj blocks)
#define XPITCH  129
#define K1_OFF_X  (FIN_ * FOUT_)               // 8192
#define K1_OFF_R1 (K1_OFF_X + 64 * XPITCH)
#define K1_OFF_R2 (K1_OFF_R1 + 256)
#define SM1_FLOATS (K1_OFF_R2 + 256)

__device__ __forceinline__ unsigned smaddr(const void* p) {
    return (unsigned)__cvta_generic_to_shared(p);
}
__device__ __forceinline__ void cpa16(unsigned s, const void* g) {
    asm volatile("cp.async.ca.shared.global [%0], [%1], 16;" :: "r"(s), "l"(g));
}
__device__ __forceinline__ void cpa_commit() {
    asm volatile("cp.async.commit_group;" ::: "memory");
}
__device__ __forceinline__ void cpa_wait0() {
    asm volatile("cp.async.wait_group 0;" ::: "memory");
}
__device__ __forceinline__ void ldsm_x4(unsigned& r0, unsigned& r1, unsigned& r2, unsigned& r3,
                                        unsigned addr) {
    asm volatile("ldmatrix.sync.aligned.m8n8.x4.shared.b16 {%0,%1,%2,%3}, [%4];"
                 : "=r"(r0), "=r"(r1), "=r"(r2), "=r"(r3) : "r"(addr));
}
__device__ __forceinline__ void ldsm_x2t(unsigned& r0, unsigned& r1, unsigned addr) {
    asm volatile("ldmatrix.sync.aligned.m8n8.x2.trans.shared.b16 {%0,%1}, [%2];"
                 : "=r"(r0), "=r"(r1) : "r"(addr));
}
__device__ __forceinline__ void mma_f16(float& c0, float& c1, float& c2, float& c3,
                                        unsigned a0, unsigned a1, unsigned a2, unsigned a3,
                                        unsigned b0, unsigned b1) {
    asm("mma.sync.aligned.m16n8k16.row.col.f32.f16.f16.f32 "
        "{%0,%1,%2,%3}, {%4,%5,%6,%7}, {%8,%9}, {%0,%1,%2,%3};"
        : "+f"(c0), "+f"(c1), "+f"(c2), "+f"(c3)
        : "r"(a0), "r"(a1), "r"(a2), "r"(a3), "r"(b0), "r"(b1));
}
__device__ __forceinline__ unsigned h2pack(float a, float b) {
    __half2 v = __floats2half2_rn(a, b);
    return *reinterpret_cast<unsigned*>(&v);
}

// -------- scratch --------
__device__ __half g_hh[BN_ * FOUT_];               // 2 MB : h in fp16
__device__ unsigned g_adjp[BN_ * (N_ / 32)];       // 4 MB : adj bit-packed along j
__device__ float g_s1[BN_], g_s2[BN_];
__device__ float g_E1[BN_], g_F1[BN_], g_E2[BN_], g_F2[BN_];
__device__ float g_acc[JSPLIT][BN_ * FOUT_];
__device__ float g_l[JSPLIT][BN_];

// ============================================================================
// Kernel 1 (fused): blocks [0,256) = h = x@W (fp16) + s1/s2 + exps;
//                   blocks [256,512) = bit-pack adj (coalesced LDG + ballot).
// The BW-bound pack overlaps the latency-bound projection across SMs.
// ============================================================================
__global__ __launch_bounds__(128) void k1_proj(const float* __restrict__ x,
                                               const float* __restrict__ W,
                                               const float* __restrict__ a,
                                               const int* __restrict__ adj) {
    const int t = threadIdx.x;

    if (blockIdx.x >= 256) {
        // ---------------- adj bit-packing path ----------------
        const int pb = blockIdx.x - 256;       // 0..255
        const int wp = t >> 5, lane = t & 31;
        const int rowbase = pb * 64 + wp * 16; // 16 rows per warp
        for (int r = 0; r < 16; ++r) {
            const size_t row = (size_t)rowbase + r;
            const int* src = adj + row * N_;
            #pragma unroll
            for (int w = 0; w < 64; w += 4) {
                unsigned m0, m1, m2, m3;
                {
                    const int v0 = src[(w + 0) * 32 + lane];
                    const int v1 = src[(w + 1) * 32 + lane];
                    const int v2 = src[(w + 2) * 32 + lane];
                    const int v3 = src[(w + 3) * 32 + lane];
                    m0 = __ballot_sync(0xffffffffu, v0 > 0);
                    m1 = __ballot_sync(0xffffffffu, v1 > 0);
                    m2 = __ballot_sync(0xffffffffu, v2 > 0);
                    m3 = __ballot_sync(0xffffffffu, v3 > 0);
                }
                if (lane == 0)
                    *reinterpret_cast<uint4*>(&g_adjp[row * 64 + w]) =
                        make_uint4(m0, m1, m2, m3);
            }
        }
        return;
    }

    // ---------------- projection path (unchanged from R9) ----------------
    extern __shared__ float sm1[];
    float* sW  = sm1;
    float* sx  = sm1 + K1_OFF_X;
    float* sr1 = sm1 + K1_OFF_R1;
    float* sr2 = sm1 + K1_OFF_R2;

    const int rowbase = blockIdx.x * 64;

    {
        float4*       d = reinterpret_cast<float4*>(sW);
        const float4* s = reinterpret_cast<const float4*>(W);
        #pragma unroll
        for (int q = 0; q < 16; ++q) d[t + q * 128] = s[t + q * 128];
    }
    {
        const float4* s = reinterpret_cast<const float4*>(x);
        #pragma unroll
        for (int q = 0; q < 16; ++q) {
            const int idx = t + q * 128;
            const int row = idx >> 5;
            const int k4  = idx & 31;
            float4 v = s[(size_t)(rowbase + row) * 32 + k4];
            float* dst = &sx[row * XPITCH + k4 * 4];
            dst[0] = v.x; dst[1] = v.y; dst[2] = v.z; dst[3] = v.w;
        }
    }
    __syncthreads();

    const int fg = t >> 5;
    const int rt = t & 31;

    float acc[2][16];
    #pragma unroll
    for (int r = 0; r < 2; ++r)
        #pragma unroll
        for (int c = 0; c < 16; ++c) acc[r][c] = 0.f;

    for (int k4 = 0; k4 < FIN_ / 4; ++k4) {
        float xs[2][4];
        #pragma unroll
        for (int rr = 0; rr < 2; ++rr) {
            const float* xr = &sx[(rt + 32 * rr) * XPITCH + k4 * 4];
            xs[rr][0] = xr[0]; xs[rr][1] = xr[1]; xs[rr][2] = xr[2]; xs[rr][3] = xr[3];
        }
        #pragma unroll
        for (int q = 0; q < 4; ++q) {
            const int k = k4 * 4 + q;
            const float4* wr = reinterpret_cast<const float4*>(&sW[k * FOUT_ + fg * 16]);
            const float4 w0 = wr[0], w1 = wr[1], w2 = wr[2], w3 = wr[3];
            #pragma unroll
            for (int rr = 0; rr < 2; ++rr) {
                const float xv = xs[rr][q];
                acc[rr][0]  += xv * w0.x; acc[rr][1]  += xv * w0.y;
                acc[rr][2]  += xv * w0.z; acc[rr][3]  += xv * w0.w;
                acc[rr][4]  += xv * w1.x; acc[rr][5]  += xv * w1.y;
                acc[rr][6]  += xv * w1.z; acc[rr][7]  += xv * w1.w;
                acc[rr][8]  += xv * w2.x; acc[rr][9]  += xv * w2.y;
                acc[rr][10] += xv * w2.z; acc[rr][11] += xv * w2.w;
                acc[rr][12] += xv * w3.x; acc[rr][13] += xv * w3.y;
                acc[rr][14] += xv * w3.z; acc[rr][15] += xv * w3.w;
            }
        }
    }

    float a1v[16], a2v[16];
    #pragma unroll
    for (int f = 0; f < 16; ++f) {
        a1v[f] = a[fg * 16 + f];
        a2v[f] = a[FOUT_ + fg * 16 + f];
    }
    #pragma unroll
    for (int rr = 0; rr < 2; ++rr) {
        const int rloc = rt + 32 * rr;
        const size_t row = (size_t)rowbase + rloc;
        uint2* hd = reinterpret_cast<uint2*>(&g_hh[row * FOUT_ + fg * 16]);
        #pragma unroll
        for (int f4 = 0; f4 < 4; ++f4) {
            hd[f4] = make_uint2(h2pack(acc[rr][f4 * 4],     acc[rr][f4 * 4 + 1]),
                                h2pack(acc[rr][f4 * 4 + 2], acc[rr][f4 * 4 + 3]));
        }
        float ps1 = 0.f, ps2 = 0.f;
        #pragma unroll
        for (int f = 0; f < 16; ++f) {
            ps1 += acc[rr][f] * a1v[f];
            ps2 += acc[rr][f] * a2v[f];
        }
        sr1[rloc * 4 + fg] = ps1;
        sr2[rloc * 4 + fg] = ps2;
    }
    __syncthreads();
    if (t < 64) {
        const int row = rowbase + t;
        const float s1 = sr1[t * 4] + sr1[t * 4 + 1] + sr1[t * 4 + 2] + sr1[t * 4 + 3];
        const float s2 = sr2[t * 4] + sr2[t * 4 + 1] + sr2[t * 4 + 2] + sr2[t * 4 + 3];
        g_s1[row] = s1;
        g_s2[row] = s2;
        g_E1[row] = expf(s1);
        g_F1[row] = expf(0.2f * s1);
        g_E2[row] = expf(s2);
        g_F2[row] = expf(0.2f * s2);
    }
}

// ============================================================================
// Kernel 2: fused masked attention + aggregation, fp16 mma + ldmatrix,
// software-pipelined; adj read from the 1-bit packed mask (uint2 per row/tile).
// ============================================================================
__global__ __launch_bounds__(256, 2) void k2_attn() {
    extern __shared__ __align__(16) char smraw[];
    __half* smHb = reinterpret_cast<__half*>(smraw);            // [2][HBUFH]
    __half* smPb = smHb + OFF_PB;                               // [2][PBUFH]
    float* s_s1 = reinterpret_cast<float*>(smraw + SM_S1_BYTE);
    float* s_E1 = s_s1 + 128;
    float* s_F1 = s_E1 + 128;

    const int t  = threadIdx.x;
    const int b  = blockIdx.y;
    const int i0 = blockIdx.x * TI;
    const int js = blockIdx.z;
    const int jbase = js * JCHUNK;
    const int nb = b * N_;

    if (t < TI) {
        const int g = nb + i0 + t;
        s_s1[t] = g_s1[g]; s_E1[t] = g_E1[g]; s_F1[t] = g_F1[g];
    }
    if (t < 128) {   // ones-column (cols 64..71) for both H buffers
        const int bufi = t >> 6, row = t & 63;
        uint4* dst = reinterpret_cast<uint4*>(&smHb[bufi * HBUFH + row * HPH + 64]);
        *dst = make_uint4(0x00003C00u, 0u, 0u, 0u);   // {fp16(1),0,...,0}
    }

    const int w    = t >> 5;
    const int lane = t & 31;
    const int grp  = lane >> 2;
    const int tig  = lane & 3;
    const int j4   = t & 15;
    const int ibA  = t >> 4;

    const int lrow8 = (lane & 7) + ((lane >> 3) & 1) * 8;
    const unsigned aoff = (unsigned)((w * 16 + lrow8) * HPH + (lane >> 4) * 8) * 2;
    const unsigned boff = (unsigned)(lrow8 * HPH) * 2;

    float acc[9][4];
    #pragma unroll
    for (int n = 0; n < 9; ++n)
        #pragma unroll
        for (int c = 0; c < 4; ++c) acc[n][c] = 0.f;

    uint2 adjreg[8];                      // 2 packed words per row (this tile's 64 j)
    float4 s2v, E2v, F2v;

    const int wb = jbase >> 5;            // word base of this j-split
    const unsigned bsh = (j4 << 2) & 31;  // bit offset of this thread's 4 j's

    // ---------------- prologue: tile 0 -> buffer 0 ----------------
    {
        const int j0 = jbase;
        #pragma unroll
        for (int q = 0; q < 2; ++q) {
            const int idx = t + q * 256;
            const int row = idx >> 3, c8 = idx & 7;
            cpa16(smaddr(&smHb[row * HPH + c8 * 8]),
                  &g_hh[(size_t)(nb + j0 + row) * FOUT_ + c8 * 8]);
        }
        cpa_commit();
        #pragma unroll
        for (int ii = 0; ii < 8; ++ii) {
            const int i = ibA + ii * 16;
            adjreg[ii] = *reinterpret_cast<const uint2*>(
                &g_adjp[(size_t)(nb + i0 + i) * 64 + wb]);
        }
        s2v = *reinterpret_cast<const float4*>(&g_s2[nb + j0 + j4 * 4]);
        E2v = *reinterpret_cast<const float4*>(&g_E2[nb + j0 + j4 * 4]);
        F2v = *reinterpret_cast<const float4*>(&g_F2[nb + j0 + j4 * 4]);
        __syncthreads();
        const float s2a[4] = {s2v.x, s2v.y, s2v.z, s2v.w};
        const float E2a[4] = {E2v.x, E2v.y, E2v.z, E2v.w};
        const float F2a[4] = {F2v.x, F2v.y, F2v.z, F2v.w};
        #pragma unroll
        for (int ii = 0; ii < 8; ++ii) {
            const int i = ibA + ii * 16;
            const float s1 = s_s1[i], E1 = s_E1[i], F1 = s_F1[i];
            const unsigned wsel = (j4 < 8) ? adjreg[ii].x : adjreg[ii].y;
            const unsigned bits = (wsel >> bsh) & 0xFu;
            float p[4];
            #pragma unroll
            for (int q = 0; q < 4; ++q) {
                const float xsum = s1 + s2a[q];
                float pv = (xsum > 0.f) ? (E1 * E2a[q]) : (F1 * F2a[q]);
                p[q] = ((bits >> q) & 1u) ? pv : 0.f;
            }
            *reinterpret_cast<uint2*>(&smPb[i * HPH + j4 * 4]) =
                make_uint2(h2pack(p[0], p[1]), h2pack(p[2], p[3]));
        }
        cpa_wait0();
        __syncthreads();
    }

    // ---------------- main pipelined loop ----------------
    for (int tt = 0; tt < NT_; ++tt) {
        const int buf = tt & 1;
        const __half* Hc = smHb + buf * HBUFH;
        const __half* Pc = smPb + buf * PBUFH;
        __half* Hn = smHb + (buf ^ 1) * HBUFH;
        __half* Pn = smPb + (buf ^ 1) * PBUFH;
        const bool more = (tt + 1 < NT_);

        if (more) {
            const int j0n = jbase + (tt + 1) * TJ;
            #pragma unroll
            for (int q = 0; q < 2; ++q) {
                const int idx = t + q * 256;
                const int row = idx >> 3, c8 = idx & 7;
                cpa16(smaddr(&Hn[row * HPH + c8 * 8]),
                      &g_hh[(size_t)(nb + j0n + row) * FOUT_ + c8 * 8]);
            }
            cpa_commit();
            const int wbn = wb + (tt + 1) * 2;
            #pragma unroll
            for (int ii = 0; ii < 8; ++ii) {
                const int i = ibA + ii * 16;
                adjreg[ii] = *reinterpret_cast<const uint2*>(
                    &g_adjp[(size_t)(nb + i0 + i) * 64 + wbn]);
            }
            s2v = *reinterpret_cast<const float4*>(&g_s2[nb + j0n + j4 * 4]);
            E2v = *reinterpret_cast<const float4*>(&g_E2[nb + j0n + j4 * 4]);
            F2v = *reinterpret_cast<const float4*>(&g_F2[nb + j0n + j4 * 4]);
        }

        // ---- Phase B: fp16 MMA over tile tt ----
        {
            const unsigned pa = smaddr(Pc) + aoff;
            const unsigned hb = smaddr(Hc) + boff;
            #pragma unroll
            for (int k0 = 0; k0 < TJ; k0 += 16) {
                unsigned a0, a1, a2, a3;
                ldsm_x4(a0, a1, a2, a3, pa + k0 * 2);
                #pragma unroll
                for (int ng = 0; ng < 9; ++ng) {
                    unsigned b0, b1;
                    ldsm_x2t(b0, b1, hb + k0 * (HPH * 2) + ng * 16);
                    mma_f16(acc[ng][0], acc[ng][1], acc[ng][2], acc[ng][3],
                            a0, a1, a2, a3, b0, b1);
                }
            }
        }

        // ---- Phase A: produce tile tt+1 ----
        if (more) {
            const float s2a[4] = {s2v.x, s2v.y, s2v.z, s2v.w};
            const float E2a[4] = {E2v.x, E2v.y, E2v.z, E2v.w};
            const float F2a[4] = {F2v.x, F2v.y, F2v.z, F2v.w};
            #pragma unroll
            for (int ii = 0; ii < 8; ++ii) {
                const int i = ibA + ii * 16;
                const float s1 = s_s1[i], E1 = s_E1[i], F1 = s_F1[i];
                const unsigned wsel = (j4 < 8) ? adjreg[ii].x : adjreg[ii].y;
                const unsigned bits = (wsel >> bsh) & 0xFu;
                float p[4];
                #pragma unroll
                for (int q = 0; q < 4; ++q) {
                    const float xsum = s1 + s2a[q];
                    float pv = (xsum > 0.f) ? (E1 * E2a[q]) : (F1 * F2a[q]);
                    p[q] = ((bits >> q) & 1u) ? pv : 0.f;
                }
                *reinterpret_cast<uint2*>(&Pn[i * HPH + j4 * 4]) =
                    make_uint2(h2pack(p[0], p[1]), h2pack(p[2], p[3]));
            }
            cpa_wait0();
        }
        __syncthreads();
    }

    // write partials
    const size_t r0 = (size_t)nb + i0 + w * 16 + grp;
    const size_t r1 = r0 + 8;
    #pragma unroll
    for (int ng = 0; ng < 8; ++ng) {
        const int f = ng * 8 + tig * 2;
        float2* d0 = reinterpret_cast<float2*>(&g_acc[js][r0 * FOUT_ + f]);
        float2* d1 = reinterpret_cast<float2*>(&g_acc[js][r1 * FOUT_ + f]);
        *d0 = make_float2(acc[ng][0], acc[ng][1]);
        *d1 = make_float2(acc[ng][2], acc[ng][3]);
    }
    if (tig == 0) {
        g_l[js][r0] = acc[8][0];
        g_l[js][r1] = acc[8][2];
    }
}

// ============================================================================
// Kernel 3: combine j-splits, normalize, LayerNorm, ELU.
// ============================================================================
__global__ __launch_bounds__(256) void k3_ln(const float* __restrict__ gamma,
                                             const float* __restrict__ beta,
                                             float* __restrict__ out) {
    const int t = threadIdx.x;
    const int warp = t >> 5, lane = t & 31;
    const int row = blockIdx.x * 8 + warp;
    const size_t base = (size_t)row * FOUT_;

    const float v0 = g_acc[0][base + lane]      + g_acc[1][base + lane];
    const float v1 = g_acc[0][base + 32 + lane] + g_acc[1][base + 32 + lane];
    const float l  = g_l[0][row] + g_l[1][row];
    const float inv = 1.f / l;
    const float h0 = v0 * inv, h1 = v1 * inv;

    float s = h0 + h1;
    #pragma unroll
    for (int o = 16; o; o >>= 1) s += __shfl_xor_sync(0xffffffffu, s, o);
    const float mu = s * (1.f / 64.f);

    const float d0 = h0 - mu, d1 = h1 - mu;
    float vs = d0 * d0 + d1 * d1;
    #pragma unroll
    for (int o = 16; o; o >>= 1) vs += __shfl_xor_sync(0xffffffffu, vs, o);
    const float rstd = rsqrtf(vs * (1.f / 64.f) + 1e-5f);

    const float y0 = d0 * rstd * gamma[lane]      + beta[lane];
    const float y1 = d1 * rstd * gamma[lane + 32] + beta[lane + 32];
    out[base + lane]      = (y0 > 0.f) ? y0 : expm1f(y0);
    out[base + 32 + lane] = (y1 > 0.f) ? y1 : expm1f(y1);
}

// ============================================================================
extern "C" void kernel_launch(void* const* d_in, const int* in_sizes, int n_in,
                              void* d_out, int out_size) {
    const float* x     = (const float*)d_in[0];
    const int*   adj   = (const int*)  d_in[1];
    const float* W     = (const float*)d_in[2];
    const float* a     = (const float*)d_in[3];
    const float* gamma = (const float*)d_in[4];
    const float* beta  = (const float*)d_in[5];
    float* out = (float*)d_out;

    const int smem1 = SM1_FLOATS * (int)sizeof(float);
    const int smem2 = SM2_BYTES;
    cudaFuncSetAttribute(k1_proj, cudaFuncAttributeMaxDynamicSharedMemorySize, smem1);
    cudaFuncSetAttribute(k2_attn, cudaFuncAttributeMaxDynamicSharedMemorySize, smem2);

    k1_proj<<<512, 128, smem1>>>(x, W, a, adj);          // 256 proj + 256 pack blocks
    k2_attn<<<dim3(N_ / TI, B_, JSPLIT), 256, smem2>>>();
    k3_ln<<<BN_ / 8, 256>>>(gamma, beta, out);
}

// round 12
// speedup vs baseline: 1.2125x; 1.2125x over previous
#include <cuda_runtime.h>
#include <cuda_fp16.h>
#include <math.h>

#define B_    8
#define N_    2048
#define FIN_  128
#define FOUT_ 64
#define BN_   (B_ * N_)

#define TI      64
#define TJ      64
#define NT_     (N_ / TJ)              // 32 tiles per block (full j range)

// ---- k2 smem: fp16 tiles pitch 72 halves (144 B, 16B-aligned rows,
//      row stride 36 banks -> conflict-free ldmatrix). No ones-column.
#define HPH     72
#define PBUFH   (TI * HPH)             // 4608 halves
#define HBUFH   (TJ * HPH)             // 4608 halves
#define OFF_H0H (2 * PBUFH)            // halves offsets: [P0][P1][H0][H1]
#define OFF_H1H (OFF_H0H + HBUFH)
#define SM_F_BYTE ((2 * PBUFH + 2 * HBUFH) * 2)     // 36864
#define SM2_BYTES (SM_F_BYTE + 4 * TI * 4)          // + s1/E1/F1/l = 37888
#define ACCP    68                     // f32 pitch for epilogue staging (reuse P area)

// ---- k1 smem (proven R9 shape) ----
#define XPITCH  129
#define K1_OFF_X  (FIN_ * FOUT_)
#define K1_OFF_R1 (K1_OFF_X + 64 * XPITCH)
#define K1_OFF_R2 (K1_OFF_R1 + 256)
#define SM1_FLOATS (K1_OFF_R2 + 256)

__device__ __forceinline__ unsigned smaddr(const void* p) {
    return (unsigned)__cvta_generic_to_shared(p);
}
__device__ __forceinline__ void cpa16(unsigned s, const void* g) {
    asm volatile("cp.async.ca.shared.global [%0], [%1], 16;" :: "r"(s), "l"(g));
}
__device__ __forceinline__ void cpa_commit() {
    asm volatile("cp.async.commit_group;" ::: "memory");
}
__device__ __forceinline__ void cpa_wait0() {
    asm volatile("cp.async.wait_group 0;" ::: "memory");
}
__device__ __forceinline__ void ldsm_x4(unsigned& r0, unsigned& r1, unsigned& r2, unsigned& r3,
                                        unsigned addr) {
    asm volatile("ldmatrix.sync.aligned.m8n8.x4.shared.b16 {%0,%1,%2,%3}, [%4];"
                 : "=r"(r0), "=r"(r1), "=r"(r2), "=r"(r3) : "r"(addr));
}
__device__ __forceinline__ void ldsm_x2t(unsigned& r0, unsigned& r1, unsigned addr) {
    asm volatile("ldmatrix.sync.aligned.m8n8.x2.trans.shared.b16 {%0,%1}, [%2];"
                 : "=r"(r0), "=r"(r1) : "r"(addr));
}
__device__ __forceinline__ void mma_f16(float& c0, float& c1, float& c2, float& c3,
                                        unsigned a0, unsigned a1, unsigned a2, unsigned a3,
                                        unsigned b0, unsigned b1) {
    asm("mma.sync.aligned.m16n8k16.row.col.f32.f16.f16.f32 "
        "{%0,%1,%2,%3}, {%4,%5,%6,%7}, {%8,%9}, {%0,%1,%2,%3};"
        : "+f"(c0), "+f"(c1), "+f"(c2), "+f"(c3)
        : "r"(a0), "r"(a1), "r"(a2), "r"(a3), "r"(b0), "r"(b1));
}
__device__ __forceinline__ unsigned h2pack(float a, float b) {
    __half2 v = __floats2half2_rn(a, b);
    return *reinterpret_cast<unsigned*>(&v);
}

// -------- scratch --------
__device__ __half g_hh[BN_ * FOUT_];               // 2 MB : h in fp16
__device__ float g_s1[BN_], g_s2[BN_];
__device__ float g_E1[BN_], g_F1[BN_], g_E2[BN_], g_F2[BN_];

// ============================================================================
// Kernel 1: h = x @ W (fp16 out) + s1/s2 dots + per-node exps.
// 256 blocks x 128 threads, 64 rows/block, 2 rows/thread (R9-proven, 15.7us).
// ============================================================================
__global__ __launch_bounds__(128) void k1_proj(const float* __restrict__ x,
                                               const float* __restrict__ W,
                                               const float* __restrict__ a) {
    extern __shared__ float sm1[];
    float* sW  = sm1;
    float* sx  = sm1 + K1_OFF_X;
    float* sr1 = sm1 + K1_OFF_R1;
    float* sr2 = sm1 + K1_OFF_R2;

    const int t = threadIdx.x;
    const int rowbase = blockIdx.x * 64;

    {
        float4*       d = reinterpret_cast<float4*>(sW);
        const float4* s = reinterpret_cast<const float4*>(W);
        #pragma unroll
        for (int q = 0; q < 16; ++q) d[t + q * 128] = s[t + q * 128];
    }
    {
        const float4* s = reinterpret_cast<const float4*>(x);
        #pragma unroll
        for (int q = 0; q < 16; ++q) {
            const int idx = t + q * 128;
            const int row = idx >> 5;
            const int k4  = idx & 31;
            float4 v = s[(size_t)(rowbase + row) * 32 + k4];
            float* dst = &sx[row * XPITCH + k4 * 4];
            dst[0] = v.x; dst[1] = v.y; dst[2] = v.z; dst[3] = v.w;
        }
    }
    __syncthreads();

    const int fg = t >> 5;
    const int rt = t & 31;

    float acc[2][16];
    #pragma unroll
    for (int r = 0; r < 2; ++r)
        #pragma unroll
        for (int c = 0; c < 16; ++c) acc[r][c] = 0.f;

    for (int k4 = 0; k4 < FIN_ / 4; ++k4) {
        float xs[2][4];
        #pragma unroll
        for (int rr = 0; rr < 2; ++rr) {
            const float* xr = &sx[(rt + 32 * rr) * XPITCH + k4 * 4];
            xs[rr][0] = xr[0]; xs[rr][1] = xr[1]; xs[rr][2] = xr[2]; xs[rr][3] = xr[3];
        }
        #pragma unroll
        for (int q = 0; q < 4; ++q) {
            const int k = k4 * 4 + q;
            const float4* wr = reinterpret_cast<const float4*>(&sW[k * FOUT_ + fg * 16]);
            const float4 w0 = wr[0], w1 = wr[1], w2 = wr[2], w3 = wr[3];
            #pragma unroll
            for (int rr = 0; rr < 2; ++rr) {
                const float xv = xs[rr][q];
                acc[rr][0]  += xv * w0.x; acc[rr][1]  += xv * w0.y;
                acc[rr][2]  += xv * w0.z; acc[rr][3]  += xv * w0.w;
                acc[rr][4]  += xv * w1.x; acc[rr][5]  += xv * w1.y;
                acc[rr][6]  += xv * w1.z; acc[rr][7]  += xv * w1.w;
                acc[rr][8]  += xv * w2.x; acc[rr][9]  += xv * w2.y;
                acc[rr][10] += xv * w2.z; acc[rr][11] += xv * w2.w;
                acc[rr][12] += xv * w3.x; acc[rr][13] += xv * w3.y;
                acc[rr][14] += xv * w3.z; acc[rr][15] += xv * w3.w;
            }
        }
    }

    float a1v[16], a2v[16];
    #pragma unroll
    for (int f = 0; f < 16; ++f) {
        a1v[f] = a[fg * 16 + f];
        a2v[f] = a[FOUT_ + fg * 16 + f];
    }
    #pragma unroll
    for (int rr = 0; rr < 2; ++rr) {
        const int rloc = rt + 32 * rr;
        const size_t row = (size_t)rowbase + rloc;
        uint2* hd = reinterpret_cast<uint2*>(&g_hh[row * FOUT_ + fg * 16]);
        #pragma unroll
        for (int f4 = 0; f4 < 4; ++f4) {
            hd[f4] = make_uint2(h2pack(acc[rr][f4 * 4],     acc[rr][f4 * 4 + 1]),
                                h2pack(acc[rr][f4 * 4 + 2], acc[rr][f4 * 4 + 3]));
        }
        float ps1 = 0.f, ps2 = 0.f;
        #pragma unroll
        for (int f = 0; f < 16; ++f) {
            ps1 += acc[rr][f] * a1v[f];
            ps2 += acc[rr][f] * a2v[f];
        }
        sr1[rloc * 4 + fg] = ps1;
        sr2[rloc * 4 + fg] = ps2;
    }
    __syncthreads();
    if (t < 64) {
        const int row = rowbase + t;
        const float s1 = sr1[t * 4] + sr1[t * 4 + 1] + sr1[t * 4 + 2] + sr1[t * 4 + 3];
        const float s2 = sr2[t * 4] + sr2[t * 4 + 1] + sr2[t * 4 + 2] + sr2[t * 4 + 3];
        g_s1[row] = s1;
        g_s2[row] = s2;
        g_E1[row] = expf(s1);
        g_F1[row] = expf(0.2f * s1);
        g_E2[row] = expf(s2);
        g_F2[row] = expf(0.2f * s2);
    }
}

// ============================================================================
// Kernel 2: fully-fused masked attention + aggregation + LayerNorm + ELU.
// TI=64 rows/CTA over ALL 2048 j (32 tiles); fp16 mma.m16n8k16 + ldmatrix,
// software-pipelined double buffers; l in fp32 registers (no ones-column);
// epilogue stages C-frags via smem, applies LN+ELU, writes out directly.
// ============================================================================
__global__ __launch_bounds__(256, 2) void k2_attn(const int* __restrict__ adj,
                                                  const float* __restrict__ gamma,
                                                  const float* __restrict__ beta,
                                                  float* __restrict__ out) {
    extern __shared__ __align__(16) char smraw[];
    __half* smPb = reinterpret_cast<__half*>(smraw);            // [2][PBUFH]
    __half* smHb = smPb + OFF_H0H;                              // [2][HBUFH]
    float* accf = reinterpret_cast<float*>(smraw);              // epilogue reuse
    float* s_s1 = reinterpret_cast<float*>(smraw + SM_F_BYTE);
    float* s_E1 = s_s1 + TI;
    float* s_F1 = s_E1 + TI;
    float* s_l  = s_F1 + TI;

    const int t  = threadIdx.x;
    const int b  = blockIdx.y;
    const int i0 = blockIdx.x * TI;
    const int nb = b * N_;

    if (t < TI) {
        const int g = nb + i0 + t;
        s_s1[t] = g_s1[g]; s_E1[t] = g_E1[g]; s_F1[t] = g_F1[g];
    }

    const int w    = t >> 5;          // 0..7
    const int lane = t & 31;
    const int grp  = lane >> 2;
    const int tig  = lane & 3;
    const int wm   = w & 3;           // row group: rows [wm*16, wm*16+16)
    const int wn   = w >> 2;          // col half:  cols [wn*32, wn*32+32)
    const int j4   = t & 15;          // phase-A j quad
    const int ibA  = t >> 4;          // phase-A i base (0..15)

    const int lrow8 = (lane & 7) + ((lane >> 3) & 1) * 8;
    const unsigned aoff = (unsigned)((wm * 16 + lrow8) * HPH + (lane >> 4) * 8) * 2;
    const unsigned boff = (unsigned)(lrow8 * HPH) * 2;

    float acc[4][4];                  // 4 n-groups (8 cols each) x C-frag
    #pragma unroll
    for (int n = 0; n < 4; ++n)
        #pragma unroll
        for (int c = 0; c < 4; ++c) acc[n][c] = 0.f;

    int4 adjreg[4];
    float4 s2v, E2v, F2v;
    float lp[4] = {0.f, 0.f, 0.f, 0.f};

    // ---------------- prologue: produce tile 0 into buffer 0 ----------------
    {
        #pragma unroll
        for (int q = 0; q < 2; ++q) {     // H(0): 64 j-rows x 128 B of fp16
            const int idx = t + q * 256;
            const int row = idx >> 3, c8 = idx & 7;
            cpa16(smaddr(&smHb[row * HPH + c8 * 8]),
                  &g_hh[(size_t)(nb + row) * FOUT_ + c8 * 8]);
        }
        cpa_commit();
        #pragma unroll
        for (int ii = 0; ii < 4; ++ii) {
            const int i = ibA + ii * 16;
            adjreg[ii] = *reinterpret_cast<const int4*>(
                adj + (size_t)(nb + i0 + i) * N_ + j4 * 4);
        }
        s2v = *reinterpret_cast<const float4*>(&g_s2[nb + j4 * 4]);
        E2v = *reinterpret_cast<const float4*>(&g_E2[nb + j4 * 4]);
        F2v = *reinterpret_cast<const float4*>(&g_F2[nb + j4 * 4]);
        __syncthreads();   // s_s1/E1/F1 visible
        const float s2a[4] = {s2v.x, s2v.y, s2v.z, s2v.w};
        const float E2a[4] = {E2v.x, E2v.y, E2v.z, E2v.w};
        const float F2a[4] = {F2v.x, F2v.y, F2v.z, F2v.w};
        #pragma unroll
        for (int ii = 0; ii < 4; ++ii) {
            const int i = ibA + ii * 16;
            const float s1 = s_s1[i], E1 = s_E1[i], F1 = s_F1[i];
            const int av[4] = {adjreg[ii].x, adjreg[ii].y, adjreg[ii].z, adjreg[ii].w};
            float p[4];
            #pragma unroll
            for (int q = 0; q < 4; ++q) {
                const float xsum = s1 + s2a[q];
                float pv = (xsum > 0.f) ? (E1 * E2a[q]) : (F1 * F2a[q]);
                p[q] = (av[q] > 0) ? pv : 0.f;
                lp[ii] += p[q];
            }
            *reinterpret_cast<uint2*>(&smPb[i * HPH + j4 * 4]) =
                make_uint2(h2pack(p[0], p[1]), h2pack(p[2], p[3]));
        }
        cpa_wait0();
        __syncthreads();
    }

    // ---------------- main pipelined loop ----------------
    for (int tt = 0; tt < NT_; ++tt) {
        const int buf = tt & 1;
        const __half* Hc = smHb + buf * HBUFH;
        const __half* Pc = smPb + buf * PBUFH;
        __half* Hn = smHb + (buf ^ 1) * HBUFH;
        __half* Pn = smPb + (buf ^ 1) * PBUFH;
        const bool more = (tt + 1 < NT_);

        if (more) {
            const int j0n = (tt + 1) * TJ;
            #pragma unroll
            for (int q = 0; q < 2; ++q) {
                const int idx = t + q * 256;
                const int row = idx >> 3, c8 = idx & 7;
                cpa16(smaddr(&Hn[row * HPH + c8 * 8]),
                      &g_hh[(size_t)(nb + j0n + row) * FOUT_ + c8 * 8]);
            }
            cpa_commit();
            #pragma unroll
            for (int ii = 0; ii < 4; ++ii) {
                const int i = ibA + ii * 16;
                adjreg[ii] = *reinterpret_cast<const int4*>(
                    adj + (size_t)(nb + i0 + i) * N_ + j0n + j4 * 4);
            }
            s2v = *reinterpret_cast<const float4*>(&g_s2[nb + j0n + j4 * 4]);
            E2v = *reinterpret_cast<const float4*>(&g_E2[nb + j0n + j4 * 4]);
            F2v = *reinterpret_cast<const float4*>(&g_F2[nb + j0n + j4 * 4]);
        }

        // ---- Phase B: fp16 MMA over tile tt (warp: 16 rows x 32 cols) ----
        {
            const unsigned pa = smaddr(Pc) + aoff;
            const unsigned hb = smaddr(Hc) + boff;
            #pragma unroll
            for (int k0 = 0; k0 < TJ; k0 += 16) {
                unsigned a0, a1, a2, a3;
                ldsm_x4(a0, a1, a2, a3, pa + k0 * 2);
                #pragma unroll
                for (int g = 0; g < 4; ++g) {
                    unsigned b0, b1;
                    ldsm_x2t(b0, b1, hb + k0 * (HPH * 2) + (wn * 4 + g) * 16);
                    mma_f16(acc[g][0], acc[g][1], acc[g][2], acc[g][3],
                            a0, a1, a2, a3, b0, b1);
                }
            }
        }

        // ---- Phase A: produce tile tt+1 ----
        if (more) {
            const float s2a[4] = {s2v.x, s2v.y, s2v.z, s2v.w};
            const float E2a[4] = {E2v.x, E2v.y, E2v.z, E2v.w};
            const float F2a[4] = {F2v.x, F2v.y, F2v.z, F2v.w};
            #pragma unroll
            for (int ii = 0; ii < 4; ++ii) {
                const int i = ibA + ii * 16;
                const float s1 = s_s1[i], E1 = s_E1[i], F1 = s_F1[i];
                const int av[4] = {adjreg[ii].x, adjreg[ii].y, adjreg[ii].z, adjreg[ii].w};
                float p[4];
                #pragma unroll
                for (int q = 0; q < 4; ++q) {
                    const float xsum = s1 + s2a[q];
                    float pv = (xsum > 0.f) ? (E1 * E2a[q]) : (F1 * F2a[q]);
                    p[q] = (av[q] > 0) ? pv : 0.f;
                    lp[ii] += p[q];
                }
                *reinterpret_cast<uint2*>(&Pn[i * HPH + j4 * 4]) =
                    make_uint2(h2pack(p[0], p[1]), h2pack(p[2], p[3]));
            }
            cpa_wait0();
        }
        __syncthreads();
    }

    // ---- l: reduce the 16 j4-partials per row; j4==0 lanes write s_l ----
    #pragma unroll
    for (int ii = 0; ii < 4; ++ii) {
        float v = lp[ii];
        v += __shfl_xor_sync(0xffffffffu, v, 1);
        v += __shfl_xor_sync(0xffffffffu, v, 2);
        v += __shfl_xor_sync(0xffffffffu, v, 4);
        v += __shfl_xor_sync(0xffffffffu, v, 8);
        if (j4 == 0) s_l[ibA + ii * 16] = v;
    }

    // ---- stage C-frags to smem (reuse P area; pitch 68 floats) ----
    {
        const int r0 = wm * 16 + grp;
        const int r1 = r0 + 8;
        #pragma unroll
        for (int g = 0; g < 4; ++g) {
            const int f = (wn * 4 + g) * 8 + tig * 2;
            accf[r0 * ACCP + f]     = acc[g][0];
            accf[r0 * ACCP + f + 1] = acc[g][1];
            accf[r1 * ACCP + f]     = acc[g][2];
            accf[r1 * ACCP + f + 1] = acc[g][3];
        }
    }
    __syncthreads();

    // ---- LN + ELU epilogue: warp w handles rows {w, w+8, ..., w+56} ----
    #pragma unroll
    for (int p = 0; p < 8; ++p) {
        const int row = w + p * 8;
        const float inv = 1.f / s_l[row];
        const float h0 = accf[row * ACCP + lane]      * inv;
        const float h1 = accf[row * ACCP + 32 + lane] * inv;

        float s = h0 + h1;
        #pragma unroll
        for (int o = 16; o; o >>= 1) s += __shfl_xor_sync(0xffffffffu, s, o);
        const float mu = s * (1.f / 64.f);

        const float d0 = h0 - mu, d1 = h1 - mu;
        float vs = d0 * d0 + d1 * d1;
        #pragma unroll
        for (int o = 16; o; o >>= 1) vs += __shfl_xor_sync(0xffffffffu, vs, o);
        const float rstd = rsqrtf(vs * (1.f / 64.f) + 1e-5f);

        const float y0 = d0 * rstd * gamma[lane]      + beta[lane];
        const float y1 = d1 * rstd * gamma[lane + 32] + beta[lane + 32];
        const size_t base = (size_t)(nb + i0 + row) * FOUT_;
        out[base + lane]      = (y0 > 0.f) ? y0 : expm1f(y0);
        out[base + 32 + lane] = (y1 > 0.f) ? y1 : expm1f(y1);
    }
}

// ============================================================================
extern "C" void kernel_launch(void* const* d_in, const int* in_sizes, int n_in,
                              void* d_out, int out_size) {
    const float* x     = (const float*)d_in[0];
    const int*   adj   = (const int*)  d_in[1];
    const float* W     = (const float*)d_in[2];
    const float* a     = (const float*)d_in[3];
    const float* gamma = (const float*)d_in[4];
    const float* beta  = (const float*)d_in[5];
    float* out = (float*)d_out;

    const int smem1 = SM1_FLOATS * (int)sizeof(float);
    const int smem2 = SM2_BYTES;                       // 37888 B
    cudaFuncSetAttribute(k1_proj, cudaFuncAttributeMaxDynamicSharedMemorySize, smem1);
    cudaFuncSetAttribute(k2_attn, cudaFuncAttributeMaxDynamicSharedMemorySize, smem2);

    k1_proj<<<BN_ / 64, 128, smem1>>>(x, W, a);
    k2_attn<<<dim3(N_ / TI, B_), 256, smem2>>>(adj, gamma, beta, out);
}

// round 13
// speedup vs baseline: 1.6987x; 1.4010x over previous
#include <cuda_runtime.h>
#include <cuda_fp16.h>
#include <math.h>

#define B_    8
#define N_    2048
#define FIN_  128
#define FOUT_ 64
#define BN_   (B_ * N_)

#define TI      128
#define TJ      64
#define JSPLIT  2
#define JCHUNK  (N_ / JSPLIT)
#define NT_     (JCHUNK / TJ)          // 16 tiles per block

// ---- k2 smem (fp16, pitch 72 halves = 144 B; row stride 36 banks -> conflict-free)
#define HPH     72
#define HBUFH   (TJ * HPH)             // 4608 halves / buffer
#define PBUFH   (TI * HPH)             // 9216 halves / buffer
#define OFF_PB  (2 * HBUFH)            // halves offset of P buffers
#define SM2_BYTES ((2 * HBUFH + 2 * PBUFH) * 2)   // 55296 B

// ---- k1 smem ----
#define XPITCH  129
#define K1_OFF_X  (FIN_ * FOUT_)
#define K1_OFF_R1 (K1_OFF_X + 64 * XPITCH)
#define K1_OFF_R2 (K1_OFF_R1 + 256)
#define SM1_FLOATS (K1_OFF_R2 + 256)

__device__ __forceinline__ unsigned smaddr(const void* p) {
    return (unsigned)__cvta_generic_to_shared(p);
}
__device__ __forceinline__ void cpa16(unsigned s, const void* g) {
    asm volatile("cp.async.ca.shared.global [%0], [%1], 16;" :: "r"(s), "l"(g));
}
__device__ __forceinline__ void cpa_commit() {
    asm volatile("cp.async.commit_group;" ::: "memory");
}
__device__ __forceinline__ void cpa_wait0() {
    asm volatile("cp.async.wait_group 0;" ::: "memory");
}
__device__ __forceinline__ void ldsm_x4(unsigned& r0, unsigned& r1, unsigned& r2, unsigned& r3,
                                        unsigned addr) {
    asm volatile("ldmatrix.sync.aligned.m8n8.x4.shared.b16 {%0,%1,%2,%3}, [%4];"
                 : "=r"(r0), "=r"(r1), "=r"(r2), "=r"(r3) : "r"(addr));
}
__device__ __forceinline__ void ldsm_x2t(unsigned& r0, unsigned& r1, unsigned addr) {
    asm volatile("ldmatrix.sync.aligned.m8n8.x2.trans.shared.b16 {%0,%1}, [%2];"
                 : "=r"(r0), "=r"(r1) : "r"(addr));
}
__device__ __forceinline__ void mma_f16(float& c0, float& c1, float& c2, float& c3,
                                        unsigned a0, unsigned a1, unsigned a2, unsigned a3,
                                        unsigned b0, unsigned b1) {
    asm("mma.sync.aligned.m16n8k16.row.col.f32.f16.f16.f32 "
        "{%0,%1,%2,%3}, {%4,%5,%6,%7}, {%8,%9}, {%0,%1,%2,%3};"
        : "+f"(c0), "+f"(c1), "+f"(c2), "+f"(c3)
        : "r"(a0), "r"(a1), "r"(a2), "r"(a3), "r"(b0), "r"(b1));
}
__device__ __forceinline__ unsigned h2pack(float a, float b) {
    __half2 v = __floats2half2_rn(a, b);
    return *reinterpret_cast<unsigned*>(&v);
}

// -------- scratch --------
__device__ __half g_hh[BN_ * FOUT_];               // 2 MB : h in fp16
__device__ float g_E1[BN_], g_F1[BN_];             // i-side exps (fp32, read once)
__device__ __half g_E2h[BN_], g_F2h[BN_];          // j-side exps (fp16, streamed)
__device__ float g_acc[JSPLIT][BN_ * FOUT_];
__device__ float g_l[JSPLIT][BN_];

// ============================================================================
// Kernel 1: h = x @ W (fp16 out) + s1/s2 dots + per-node exps.
// 256 blocks x 128 threads, 64 rows/block, 2 rows/thread (proven 15.7us).
// ============================================================================
__global__ __launch_bounds__(128) void k1_proj(const float* __restrict__ x,
                                               const float* __restrict__ W,
                                               const float* __restrict__ a) {
    extern __shared__ float sm1[];
    float* sW  = sm1;
    float* sx  = sm1 + K1_OFF_X;
    float* sr1 = sm1 + K1_OFF_R1;
    float* sr2 = sm1 + K1_OFF_R2;

    const int t = threadIdx.x;
    const int rowbase = blockIdx.x * 64;

    {
        float4*       d = reinterpret_cast<float4*>(sW);
        const float4* s = reinterpret_cast<const float4*>(W);
        #pragma unroll
        for (int q = 0; q < 16; ++q) d[t + q * 128] = s[t + q * 128];
    }
    {
        const float4* s = reinterpret_cast<const float4*>(x);
        #pragma unroll
        for (int q = 0; q < 16; ++q) {
            const int idx = t + q * 128;
            const int row = idx >> 5;
            const int k4  = idx & 31;
            float4 v = s[(size_t)(rowbase + row) * 32 + k4];
            float* dst = &sx[row * XPITCH + k4 * 4];
            dst[0] = v.x; dst[1] = v.y; dst[2] = v.z; dst[3] = v.w;
        }
    }
    __syncthreads();

    const int fg = t >> 5;
    const int rt = t & 31;

    float acc[2][16];
    #pragma unroll
    for (int r = 0; r < 2; ++r)
        #pragma unroll
        for (int c = 0; c < 16; ++c) acc[r][c] = 0.f;

    for (int k4 = 0; k4 < FIN_ / 4; ++k4) {
        float xs[2][4];
        #pragma unroll
        for (int rr = 0; rr < 2; ++rr) {
            const float* xr = &sx[(rt + 32 * rr) * XPITCH + k4 * 4];
            xs[rr][0] = xr[0]; xs[rr][1] = xr[1]; xs[rr][2] = xr[2]; xs[rr][3] = xr[3];
        }
        #pragma unroll
        for (int q = 0; q < 4; ++q) {
            const int k = k4 * 4 + q;
            const float4* wr = reinterpret_cast<const float4*>(&sW[k * FOUT_ + fg * 16]);
            const float4 w0 = wr[0], w1 = wr[1], w2 = wr[2], w3 = wr[3];
            #pragma unroll
            for (int rr = 0; rr < 2; ++rr) {
                const float xv = xs[rr][q];
                acc[rr][0]  += xv * w0.x; acc[rr][1]  += xv * w0.y;
                acc[rr][2]  += xv * w0.z; acc[rr][3]  += xv * w0.w;
                acc[rr][4]  += xv * w1.x; acc[rr][5]  += xv * w1.y;
                acc[rr][6]  += xv * w1.z; acc[rr][7]  += xv * w1.w;
                acc[rr][8]  += xv * w2.x; acc[rr][9]  += xv * w2.y;
                acc[rr][10] += xv * w2.z; acc[rr][11] += xv * w2.w;
                acc[rr][12] += xv * w3.x; acc[rr][13] += xv * w3.y;
                acc[rr][14] += xv * w3.z; acc[rr][15] += xv * w3.w;
            }
        }
    }

    float a1v[16], a2v[16];
    #pragma unroll
    for (int f = 0; f < 16; ++f) {
        a1v[f] = a[fg * 16 + f];
        a2v[f] = a[FOUT_ + fg * 16 + f];
    }
    #pragma unroll
    for (int rr = 0; rr < 2; ++rr) {
        const int rloc = rt + 32 * rr;
        const size_t row = (size_t)rowbase + rloc;
        uint2* hd = reinterpret_cast<uint2*>(&g_hh[row * FOUT_ + fg * 16]);
        #pragma unroll
        for (int f4 = 0; f4 < 4; ++f4) {
            hd[f4] = make_uint2(h2pack(acc[rr][f4 * 4],     acc[rr][f4 * 4 + 1]),
                                h2pack(acc[rr][f4 * 4 + 2], acc[rr][f4 * 4 + 3]));
        }
        float ps1 = 0.f, ps2 = 0.f;
        #pragma unroll
        for (int f = 0; f < 16; ++f) {
            ps1 += acc[rr][f] * a1v[f];
            ps2 += acc[rr][f] * a2v[f];
        }
        sr1[rloc * 4 + fg] = ps1;
        sr2[rloc * 4 + fg] = ps2;
    }
    __syncthreads();
    if (t < 64) {
        const int row = rowbase + t;
        const float s1 = sr1[t * 4] + sr1[t * 4 + 1] + sr1[t * 4 + 2] + sr1[t * 4 + 3];
        const float s2 = sr2[t * 4] + sr2[t * 4 + 1] + sr2[t * 4 + 2] + sr2[t * 4 + 3];
        g_E1[row]  = expf(s1);
        g_F1[row]  = expf(0.2f * s1);
        g_E2h[row] = __float2half(expf(s2));
        g_F2h[row] = __float2half(expf(0.2f * s2));
    }
}

// ============================================================================
// Kernel 2: fused masked attention + aggregation, fp16 mma + ldmatrix,
// software-pipelined (R9 structure). Phase A minimized:
//   p = adjmask * max(E1*E2, F1*F2)   -- branch-free packed half2 math,
// E1/F1 hoisted to per-thread replicated-half2 registers (tile-invariant).
// Ones-column in H gives l via the (idle) tensor pipe.
// ============================================================================
__global__ __launch_bounds__(256, 2) void k2_attn(const int* __restrict__ adj) {
    extern __shared__ __align__(16) char smraw[];
    __half* smHb = reinterpret_cast<__half*>(smraw);            // [2][HBUFH]
    __half* smPb = smHb + OFF_PB;                               // [2][PBUFH]

    const int t  = threadIdx.x;
    const int b  = blockIdx.y;
    const int i0 = blockIdx.x * TI;
    const int js = blockIdx.z;
    const int jbase = js * JCHUNK;
    const int nb = b * N_;

    if (t < 128) {   // ones-column (cols 64..71) for both H buffers
        const int bufi = t >> 6, row = t & 63;
        uint4* dst = reinterpret_cast<uint4*>(&smHb[bufi * HBUFH + row * HPH + 64]);
        *dst = make_uint4(0x00003C00u, 0u, 0u, 0u);   // {fp16(1),0,...,0}
    }

    const int w    = t >> 5;
    const int lane = t & 31;
    const int grp  = lane >> 2;
    const int tig  = lane & 3;
    const int j4   = t & 15;
    const int ibA  = t >> 4;

    // hoisted i-side exps: replicated half2, tile-invariant per thread
    __half2 E1r[8], F1r[8];
    #pragma unroll
    for (int ii = 0; ii < 8; ++ii) {
        const int gi = nb + i0 + ibA + ii * 16;
        E1r[ii] = __float2half2_rn(g_E1[gi]);
        F1r[ii] = __float2half2_rn(g_F1[gi]);
    }

    const int lrow8 = (lane & 7) + ((lane >> 3) & 1) * 8;
    const unsigned aoff = (unsigned)((w * 16 + lrow8) * HPH + (lane >> 4) * 8) * 2;
    const unsigned boff = (unsigned)(lrow8 * HPH) * 2;

    float acc[9][4];
    #pragma unroll
    for (int n = 0; n < 9; ++n)
        #pragma unroll
        for (int c = 0; c < 4; ++c) acc[n][c] = 0.f;

    int4 adjreg[8];
    uint2 e2p, f2p;

    // ---------------- prologue: produce tile 0 into buffer 0 ----------------
    {
        const int j0 = jbase;
        #pragma unroll
        for (int q = 0; q < 2; ++q) {     // H(0): 64 rows x 128 B fp16
            const int idx = t + q * 256;
            const int row = idx >> 3, c8 = idx & 7;
            cpa16(smaddr(&smHb[row * HPH + c8 * 8]),
                  &g_hh[(size_t)(nb + j0 + row) * FOUT_ + c8 * 8]);
        }
        cpa_commit();
        #pragma unroll
        for (int ii = 0; ii < 8; ++ii) {
            const int i = ibA + ii * 16;
            adjreg[ii] = *reinterpret_cast<const int4*>(
                adj + (size_t)(nb + i0 + i) * N_ + j0 + j4 * 4);
        }
        e2p = *reinterpret_cast<const uint2*>(&g_E2h[nb + j0 + j4 * 4]);
        f2p = *reinterpret_cast<const uint2*>(&g_F2h[nb + j0 + j4 * 4]);
        __syncthreads();   // ones-columns visible
        const __half2 e2lo = *reinterpret_cast<const __half2*>(&e2p.x);
        const __half2 e2hi = *reinterpret_cast<const __half2*>(&e2p.y);
        const __half2 f2lo = *reinterpret_cast<const __half2*>(&f2p.x);
        const __half2 f2hi = *reinterpret_cast<const __half2*>(&f2p.y);
        #pragma unroll
        for (int ii = 0; ii < 8; ++ii) {
            const int i = ibA + ii * 16;
            const unsigned m01 = __byte_perm((unsigned)adjreg[ii].x,
                                             (unsigned)adjreg[ii].y, 0x5410) * 0x3C00u;
            const unsigned m23 = __byte_perm((unsigned)adjreg[ii].z,
                                             (unsigned)adjreg[ii].w, 0x5410) * 0x3C00u;
            __half2 p01 = __hmul2(__hmax2(__hmul2(E1r[ii], e2lo), __hmul2(F1r[ii], f2lo)),
                                  *reinterpret_cast<const __half2*>(&m01));
            __half2 p23 = __hmul2(__hmax2(__hmul2(E1r[ii], e2hi), __hmul2(F1r[ii], f2hi)),
                                  *reinterpret_cast<const __half2*>(&m23));
            *reinterpret_cast<uint2*>(&smPb[i * HPH + j4 * 4]) =
                make_uint2(*reinterpret_cast<unsigned*>(&p01),
                           *reinterpret_cast<unsigned*>(&p23));
        }
        cpa_wait0();
        __syncthreads();
    }

    // ---------------- main pipelined loop ----------------
    for (int tt = 0; tt < NT_; ++tt) {
        const int buf = tt & 1;
        const __half* Hc = smHb + buf * HBUFH;
        const __half* Pc = smPb + buf * PBUFH;
        __half* Hn = smHb + (buf ^ 1) * HBUFH;
        __half* Pn = smPb + (buf ^ 1) * PBUFH;
        const bool more = (tt + 1 < NT_);

        if (more) {
            const int j0n = jbase + (tt + 1) * TJ;
            #pragma unroll
            for (int q = 0; q < 2; ++q) {
                const int idx = t + q * 256;
                const int row = idx >> 3, c8 = idx & 7;
                cpa16(smaddr(&Hn[row * HPH + c8 * 8]),
                      &g_hh[(size_t)(nb + j0n + row) * FOUT_ + c8 * 8]);
            }
            cpa_commit();
            #pragma unroll
            for (int ii = 0; ii < 8; ++ii) {
                const int i = ibA + ii * 16;
                adjreg[ii] = *reinterpret_cast<const int4*>(
                    adj + (size_t)(nb + i0 + i) * N_ + j0n + j4 * 4);
            }
            e2p = *reinterpret_cast<const uint2*>(&g_E2h[nb + j0n + j4 * 4]);
            f2p = *reinterpret_cast<const uint2*>(&g_F2h[nb + j0n + j4 * 4]);
        }

        // ---- Phase B: fp16 MMA over tile tt ----
        {
            const unsigned pa = smaddr(Pc) + aoff;
            const unsigned hb = smaddr(Hc) + boff;
            #pragma unroll
            for (int k0 = 0; k0 < TJ; k0 += 16) {
                unsigned a0, a1, a2, a3;
                ldsm_x4(a0, a1, a2, a3, pa + k0 * 2);
                #pragma unroll
                for (int ng = 0; ng < 9; ++ng) {
                    unsigned b0, b1;
                    ldsm_x2t(b0, b1, hb + k0 * (HPH * 2) + ng * 16);
                    mma_f16(acc[ng][0], acc[ng][1], acc[ng][2], acc[ng][3],
                            a0, a1, a2, a3, b0, b1);
                }
            }
        }

        // ---- Phase A: produce tile tt+1 (branch-free packed fp16) ----
        if (more) {
            const __half2 e2lo = *reinterpret_cast<const __half2*>(&e2p.x);
            const __half2 e2hi = *reinterpret_cast<const __half2*>(&e2p.y);
            const __half2 f2lo = *reinterpret_cast<const __half2*>(&f2p.x);
            const __half2 f2hi = *reinterpret_cast<const __half2*>(&f2p.y);
            #pragma unroll
            for (int ii = 0; ii < 8; ++ii) {
                const int i = ibA + ii * 16;
                const unsigned m01 = __byte_perm((unsigned)adjreg[ii].x,
                                                 (unsigned)adjreg[ii].y, 0x5410) * 0x3C00u;
                const unsigned m23 = __byte_perm((unsigned)adjreg[ii].z,
                                                 (unsigned)adjreg[ii].w, 0x5410) * 0x3C00u;
                __half2 p01 = __hmul2(__hmax2(__hmul2(E1r[ii], e2lo), __hmul2(F1r[ii], f2lo)),
                                      *reinterpret_cast<const __half2*>(&m01));
                __half2 p23 = __hmul2(__hmax2(__hmul2(E1r[ii], e2hi), __hmul2(F1r[ii], f2hi)),
                                      *reinterpret_cast<const __half2*>(&m23));
                *reinterpret_cast<uint2*>(&Pn[i * HPH + j4 * 4]) =
                    make_uint2(*reinterpret_cast<unsigned*>(&p01),
                               *reinterpret_cast<unsigned*>(&p23));
            }
            cpa_wait0();
        }
        __syncthreads();
    }

    // write partials (C-frag layout: m16n8 f32)
    const size_t r0 = (size_t)nb + i0 + w * 16 + grp;
    const size_t r1 = r0 + 8;
    #pragma unroll
    for (int ng = 0; ng < 8; ++ng) {
        const int f = ng * 8 + tig * 2;
        float2* d0 = reinterpret_cast<float2*>(&g_acc[js][r0 * FOUT_ + f]);
        float2* d1 = reinterpret_cast<float2*>(&g_acc[js][r1 * FOUT_ + f]);
        *d0 = make_float2(acc[ng][0], acc[ng][1]);
        *d1 = make_float2(acc[ng][2], acc[ng][3]);
    }
    if (tig == 0) {   // ones-column: col 64 holds l
        g_l[js][r0] = acc[8][0];
        g_l[js][r1] = acc[8][2];
    }
}

// ============================================================================
// Kernel 3: combine j-splits, normalize, LayerNorm, ELU.
// ============================================================================
__global__ __launch_bounds__(256) void k3_ln(const float* __restrict__ gamma,
                                             const float* __restrict__ beta,
                                             float* __restrict__ out) {
    const int t = threadIdx.x;
    const int warp = t >> 5, lane = t & 31;
    const int row = blockIdx.x * 8 + warp;
    const size_t base = (size_t)row * FOUT_;

    const float v0 = g_acc[0][base + lane]      + g_acc[1][base + lane];
    const float v1 = g_acc[0][base + 32 + lane] + g_acc[1][base + 32 + lane];
    const float l  = g_l[0][row] + g_l[1][row];
    const float inv = 1.f / l;
    const float h0 = v0 * inv, h1 = v1 * inv;

    float s = h0 + h1;
    #pragma unroll
    for (int o = 16; o; o >>= 1) s += __shfl_xor_sync(0xffffffffu, s, o);
    const float mu = s * (1.f / 64.f);

    const float d0 = h0 - mu, d1 = h1 - mu;
    float vs = d0 * d0 + d1 * d1;
    #pragma unroll
    for (int o = 16; o; o >>= 1) vs += __shfl_xor_sync(0xffffffffu, vs, o);
    const float rstd = rsqrtf(vs * (1.f / 64.f) + 1e-5f);

    const float y0 = d0 * rstd * gamma[lane]      + beta[lane];
    const float y1 = d1 * rstd * gamma[lane + 32] + beta[lane + 32];
    out[base + lane]      = (y0 > 0.f) ? y0 : expm1f(y0);
    out[base + 32 + lane] = (y1 > 0.f) ? y1 : expm1f(y1);
}

// ============================================================================
extern "C" void kernel_launch(void* const* d_in, const int* in_sizes, int n_in,
                              void* d_out, int out_size) {
    const float* x     = (const float*)d_in[0];
    const int*   adj   = (const int*)  d_in[1];
    const float* W     = (const float*)d_in[2];
    const float* a     = (const float*)d_in[3];
    const float* gamma = (const float*)d_in[4];
    const float* beta  = (const float*)d_in[5];
    float* out = (float*)d_out;

    const int smem1 = SM1_FLOATS * (int)sizeof(float);
    const int smem2 = SM2_BYTES;                       // 55296 B
    cudaFuncSetAttribute(k1_proj, cudaFuncAttributeMaxDynamicSharedMemorySize, smem1);
    cudaFuncSetAttribute(k2_attn, cudaFuncAttributeMaxDynamicSharedMemorySize, smem2);

    k1_proj<<<BN_ / 64, 128, smem1>>>(x, W, a);
    k2_attn<<<dim3(N_ / TI, B_, JSPLIT), 256, smem2>>>(adj);
    k3_ln<<<BN_ / 8, 256>>>(gamma, beta, out);
}

// round 14
// speedup vs baseline: 1.7523x; 1.0316x over previous
#include <cuda_runtime.h>
#include <cuda_fp16.h>
#include <math.h>

#define B_    8
#define N_    2048
#define FIN_  128
#define FOUT_ 64
#define BN_   (B_ * N_)

#define TI      128
#define TJ      64
#define JSPLIT  2
#define JCHUNK  (N_ / JSPLIT)
#define NT_     (JCHUNK / TJ)          // 16 tiles per block

// ---- k2 smem (fp16, pitch 72 halves = 144 B; row stride 36 banks -> conflict-free)
#define HPH     72
#define HBUFH   (TJ * HPH)             // 4608 halves / buffer
#define PBUFH   (TI * HPH)             // 9216 halves / buffer
#define OFF_PB  (2 * HBUFH)            // halves offset of P buffers
#define SM2_BYTES ((2 * HBUFH + 2 * PBUFH) * 2)   // 55296 B

// ---- k1 smem ----
#define XPITCH  129
#define K1_OFF_X  (FIN_ * FOUT_)
#define K1_OFF_R1 (K1_OFF_X + 64 * XPITCH)
#define K1_OFF_R2 (K1_OFF_R1 + 256)
#define SM1_FLOATS (K1_OFF_R2 + 256)

__device__ __forceinline__ unsigned smaddr(const void* p) {
    return (unsigned)__cvta_generic_to_shared(p);
}
__device__ __forceinline__ void cpa16(unsigned s, const void* g) {
    asm volatile("cp.async.ca.shared.global [%0], [%1], 16;" :: "r"(s), "l"(g));
}
__device__ __forceinline__ void cpa_commit() {
    asm volatile("cp.async.commit_group;" ::: "memory");
}
__device__ __forceinline__ void cpa_wait0() {
    asm volatile("cp.async.wait_group 0;" ::: "memory");
}
__device__ __forceinline__ void ldsm_x4(unsigned& r0, unsigned& r1, unsigned& r2, unsigned& r3,
                                        unsigned addr) {
    asm volatile("ldmatrix.sync.aligned.m8n8.x4.shared.b16 {%0,%1,%2,%3}, [%4];"
                 : "=r"(r0), "=r"(r1), "=r"(r2), "=r"(r3) : "r"(addr));
}
__device__ __forceinline__ void ldsm_x2t(unsigned& r0, unsigned& r1, unsigned addr) {
    asm volatile("ldmatrix.sync.aligned.m8n8.x2.trans.shared.b16 {%0,%1}, [%2];"
                 : "=r"(r0), "=r"(r1) : "r"(addr));
}
__device__ __forceinline__ void mma_f16(float& c0, float& c1, float& c2, float& c3,
                                        unsigned a0, unsigned a1, unsigned a2, unsigned a3,
                                        unsigned b0, unsigned b1) {
    asm("mma.sync.aligned.m16n8k16.row.col.f32.f16.f16.f32 "
        "{%0,%1,%2,%3}, {%4,%5,%6,%7}, {%8,%9}, {%0,%1,%2,%3};"
        : "+f"(c0), "+f"(c1), "+f"(c2), "+f"(c3)
        : "r"(a0), "r"(a1), "r"(a2), "r"(a3), "r"(b0), "r"(b1));
}
__device__ __forceinline__ unsigned h2pack(float a, float b) {
    __half2 v = __floats2half2_rn(a, b);
    return *reinterpret_cast<unsigned*>(&v);
}

// -------- scratch --------
__device__ __half g_hh[BN_ * FOUT_];               // 2 MB : h in fp16
__device__ float g_E1[BN_], g_F1[BN_];             // i-side exps (fp32, read once)
__device__ __half g_E2h[BN_], g_F2h[BN_];          // j-side exps (fp16, streamed)
__device__ float g_acc[JSPLIT][BN_ * FOUT_];
__device__ float g_l[JSPLIT][BN_];

// ============================================================================
// Kernel 1: h = x @ W (fp16 out) + s1/s2 dots + per-node exps.
// 256 blocks x 128 threads, 64 rows/block, 2 rows/thread (proven 15.7us).
// ============================================================================
__global__ __launch_bounds__(128) void k1_proj(const float* __restrict__ x,
                                               const float* __restrict__ W,
                                               const float* __restrict__ a) {
    extern __shared__ float sm1[];
    float* sW  = sm1;
    float* sx  = sm1 + K1_OFF_X;
    float* sr1 = sm1 + K1_OFF_R1;
    float* sr2 = sm1 + K1_OFF_R2;

    const int t = threadIdx.x;
    const int rowbase = blockIdx.x * 64;

    {
        float4*       d = reinterpret_cast<float4*>(sW);
        const float4* s = reinterpret_cast<const float4*>(W);
        #pragma unroll
        for (int q = 0; q < 16; ++q) d[t + q * 128] = s[t + q * 128];
    }
    {
        const float4* s = reinterpret_cast<const float4*>(x);
        #pragma unroll
        for (int q = 0; q < 16; ++q) {
            const int idx = t + q * 128;
            const int row = idx >> 5;
            const int k4  = idx & 31;
            float4 v = s[(size_t)(rowbase + row) * 32 + k4];
            float* dst = &sx[row * XPITCH + k4 * 4];
            dst[0] = v.x; dst[1] = v.y; dst[2] = v.z; dst[3] = v.w;
        }
    }
    __syncthreads();

    const int fg = t >> 5;
    const int rt = t & 31;

    float acc[2][16];
    #pragma unroll
    for (int r = 0; r < 2; ++r)
        #pragma unroll
        for (int c = 0; c < 16; ++c) acc[r][c] = 0.f;

    for (int k4 = 0; k4 < FIN_ / 4; ++k4) {
        float xs[2][4];
        #pragma unroll
        for (int rr = 0; rr < 2; ++rr) {
            const float* xr = &sx[(rt + 32 * rr) * XPITCH + k4 * 4];
            xs[rr][0] = xr[0]; xs[rr][1] = xr[1]; xs[rr][2] = xr[2]; xs[rr][3] = xr[3];
        }
        #pragma unroll
        for (int q = 0; q < 4; ++q) {
            const int k = k4 * 4 + q;
            const float4* wr = reinterpret_cast<const float4*>(&sW[k * FOUT_ + fg * 16]);
            const float4 w0 = wr[0], w1 = wr[1], w2 = wr[2], w3 = wr[3];
            #pragma unroll
            for (int rr = 0; rr < 2; ++rr) {
                const float xv = xs[rr][q];
                acc[rr][0]  += xv * w0.x; acc[rr][1]  += xv * w0.y;
                acc[rr][2]  += xv * w0.z; acc[rr][3]  += xv * w0.w;
                acc[rr][4]  += xv * w1.x; acc[rr][5]  += xv * w1.y;
                acc[rr][6]  += xv * w1.z; acc[rr][7]  += xv * w1.w;
                acc[rr][8]  += xv * w2.x; acc[rr][9]  += xv * w2.y;
                acc[rr][10] += xv * w2.z; acc[rr][11] += xv * w2.w;
                acc[rr][12] += xv * w3.x; acc[rr][13] += xv * w3.y;
                acc[rr][14] += xv * w3.z; acc[rr][15] += xv * w3.w;
            }
        }
    }

    float a1v[16], a2v[16];
    #pragma unroll
    for (int f = 0; f < 16; ++f) {
        a1v[f] = a[fg * 16 + f];
        a2v[f] = a[FOUT_ + fg * 16 + f];
    }
    #pragma unroll
    for (int rr = 0; rr < 2; ++rr) {
        const int rloc = rt + 32 * rr;
        const size_t row = (size_t)rowbase + rloc;
        uint2* hd = reinterpret_cast<uint2*>(&g_hh[row * FOUT_ + fg * 16]);
        #pragma unroll
        for (int f4 = 0; f4 < 4; ++f4) {
            hd[f4] = make_uint2(h2pack(acc[rr][f4 * 4],     acc[rr][f4 * 4 + 1]),
                                h2pack(acc[rr][f4 * 4 + 2], acc[rr][f4 * 4 + 3]));
        }
        float ps1 = 0.f, ps2 = 0.f;
        #pragma unroll
        for (int f = 0; f < 16; ++f) {
            ps1 += acc[rr][f] * a1v[f];
            ps2 += acc[rr][f] * a2v[f];
        }
        sr1[rloc * 4 + fg] = ps1;
        sr2[rloc * 4 + fg] = ps2;
    }
    __syncthreads();
    if (t < 64) {
        const int row = rowbase + t;
        const float s1 = sr1[t * 4] + sr1[t * 4 + 1] + sr1[t * 4 + 2] + sr1[t * 4 + 3];
        const float s2 = sr2[t * 4] + sr2[t * 4 + 1] + sr2[t * 4 + 2] + sr2[t * 4 + 3];
        g_E1[row]  = expf(s1);
        g_F1[row]  = expf(0.2f * s1);
        g_E2h[row] = __float2half(expf(s2));
        g_F2h[row] = __float2half(expf(0.2f * s2));
    }
}

// ============================================================================
// Kernel 2: fused masked attention + aggregation, fp16 mma + ldmatrix,
// software-pipelined (R9 structure). Phase A minimized:
//   p = adjmask * max(E1*E2, F1*F2)   -- branch-free packed half2 math,
// E1/F1 hoisted to per-thread replicated-half2 registers (tile-invariant).
// Ones-column in H gives l via the (idle) tensor pipe.
// ============================================================================
__global__ __launch_bounds__(256, 2) void k2_attn(const int* __restrict__ adj) {
    extern __shared__ __align__(16) char smraw[];
    __half* smHb = reinterpret_cast<__half*>(smraw);            // [2][HBUFH]
    __half* smPb = smHb + OFF_PB;                               // [2][PBUFH]

    const int t  = threadIdx.x;
    const int b  = blockIdx.y;
    const int i0 = blockIdx.x * TI;
    const int js = blockIdx.z;
    const int jbase = js * JCHUNK;
    const int nb = b * N_;

    if (t < 128) {   // ones-column (cols 64..71) for both H buffers
        const int bufi = t >> 6, row = t & 63;
        uint4* dst = reinterpret_cast<uint4*>(&smHb[bufi * HBUFH + row * HPH + 64]);
        *dst = make_uint4(0x00003C00u, 0u, 0u, 0u);   // {fp16(1),0,...,0}
    }

    const int w    = t >> 5;
    const int lane = t & 31;
    const int grp  = lane >> 2;
    const int tig  = lane & 3;
    const int j4   = t & 15;
    const int ibA  = t >> 4;

    // hoisted i-side exps: replicated half2, tile-invariant per thread
    __half2 E1r[8], F1r[8];
    #pragma unroll
    for (int ii = 0; ii < 8; ++ii) {
        const int gi = nb + i0 + ibA + ii * 16;
        E1r[ii] = __float2half2_rn(g_E1[gi]);
        F1r[ii] = __float2half2_rn(g_F1[gi]);
    }

    const int lrow8 = (lane & 7) + ((lane >> 3) & 1) * 8;
    const unsigned aoff = (unsigned)((w * 16 + lrow8) * HPH + (lane >> 4) * 8) * 2;
    const unsigned boff = (unsigned)(lrow8 * HPH) * 2;

    float acc[9][4];
    #pragma unroll
    for (int n = 0; n < 9; ++n)
        #pragma unroll
        for (int c = 0; c < 4; ++c) acc[n][c] = 0.f;

    int4 adjreg[8];
    uint2 e2p, f2p;

    // ---------------- prologue: produce tile 0 into buffer 0 ----------------
    {
        const int j0 = jbase;
        #pragma unroll
        for (int q = 0; q < 2; ++q) {     // H(0): 64 rows x 128 B fp16
            const int idx = t + q * 256;
            const int row = idx >> 3, c8 = idx & 7;
            cpa16(smaddr(&smHb[row * HPH + c8 * 8]),
                  &g_hh[(size_t)(nb + j0 + row) * FOUT_ + c8 * 8]);
        }
        cpa_commit();
        #pragma unroll
        for (int ii = 0; ii < 8; ++ii) {
            const int i = ibA + ii * 16;
            adjreg[ii] = *reinterpret_cast<const int4*>(
                adj + (size_t)(nb + i0 + i) * N_ + j0 + j4 * 4);
        }
        e2p = *reinterpret_cast<const uint2*>(&g_E2h[nb + j0 + j4 * 4]);
        f2p = *reinterpret_cast<const uint2*>(&g_F2h[nb + j0 + j4 * 4]);
        __syncthreads();   // ones-columns visible
        const __half2 e2lo = *reinterpret_cast<const __half2*>(&e2p.x);
        const __half2 e2hi = *reinterpret_cast<const __half2*>(&e2p.y);
        const __half2 f2lo = *reinterpret_cast<const __half2*>(&f2p.x);
        const __half2 f2hi = *reinterpret_cast<const __half2*>(&f2p.y);
        #pragma unroll
        for (int ii = 0; ii < 8; ++ii) {
            const int i = ibA + ii * 16;
            const unsigned m01 = __byte_perm((unsigned)adjreg[ii].x,
                                             (unsigned)adjreg[ii].y, 0x5410) * 0x3C00u;
            const unsigned m23 = __byte_perm((unsigned)adjreg[ii].z,
                                             (unsigned)adjreg[ii].w, 0x5410) * 0x3C00u;
            __half2 p01 = __hmul2(__hmax2(__hmul2(E1r[ii], e2lo), __hmul2(F1r[ii], f2lo)),
                                  *reinterpret_cast<const __half2*>(&m01));
            __half2 p23 = __hmul2(__hmax2(__hmul2(E1r[ii], e2hi), __hmul2(F1r[ii], f2hi)),
                                  *reinterpret_cast<const __half2*>(&m23));
            *reinterpret_cast<uint2*>(&smPb[i * HPH + j4 * 4]) =
                make_uint2(*reinterpret_cast<unsigned*>(&p01),
                           *reinterpret_cast<unsigned*>(&p23));
        }
        cpa_wait0();
        __syncthreads();
    }

    // ---------------- main pipelined loop ----------------
    for (int tt = 0; tt < NT_; ++tt) {
        const int buf = tt & 1;
        const __half* Hc = smHb + buf * HBUFH;
        const __half* Pc = smPb + buf * PBUFH;
        __half* Hn = smHb + (buf ^ 1) * HBUFH;
        __half* Pn = smPb + (buf ^ 1) * PBUFH;
        const bool more = (tt + 1 < NT_);

        if (more) {
            const int j0n = jbase + (tt + 1) * TJ;
            #pragma unroll
            for (int q = 0; q < 2; ++q) {
                const int idx = t + q * 256;
                const int row = idx >> 3, c8 = idx & 7;
                cpa16(smaddr(&Hn[row * HPH + c8 * 8]),
                      &g_hh[(size_t)(nb + j0n + row) * FOUT_ + c8 * 8]);
            }
            cpa_commit();
            #pragma unroll
            for (int ii = 0; ii < 8; ++ii) {
                const int i = ibA + ii * 16;
                adjreg[ii] = *reinterpret_cast<const int4*>(
                    adj + (size_t)(nb + i0 + i) * N_ + j0n + j4 * 4);
            }
            e2p = *reinterpret_cast<const uint2*>(&g_E2h[nb + j0n + j4 * 4]);
            f2p = *reinterpret_cast<const uint2*>(&g_F2h[nb + j0n + j4 * 4]);
        }

        // ---- Phase B: fp16 MMA over tile tt ----
        {
            const unsigned pa = smaddr(Pc) + aoff;
            const unsigned hb = smaddr(Hc) + boff;
            #pragma unroll
            for (int k0 = 0; k0 < TJ; k0 += 16) {
                unsigned a0, a1, a2, a3;
                ldsm_x4(a0, a1, a2, a3, pa + k0 * 2);
                #pragma unroll
                for (int ng = 0; ng < 9; ++ng) {
                    unsigned b0, b1;
                    ldsm_x2t(b0, b1, hb + k0 * (HPH * 2) + ng * 16);
                    mma_f16(acc[ng][0], acc[ng][1], acc[ng][2], acc[ng][3],
                            a0, a1, a2, a3, b0, b1);
                }
            }
        }

        // ---- Phase A: produce tile tt+1 (branch-free packed fp16) ----
        if (more) {
            const __half2 e2lo = *reinterpret_cast<const __half2*>(&e2p.x);
            const __half2 e2hi = *reinterpret_cast<const __half2*>(&e2p.y);
            const __half2 f2lo = *reinterpret_cast<const __half2*>(&f2p.x);
            const __half2 f2hi = *reinterpret_cast<const __half2*>(&f2p.y);
            #pragma unroll
            for (int ii = 0; ii < 8; ++ii) {
                const int i = ibA + ii * 16;
                const unsigned m01 = __byte_perm((unsigned)adjreg[ii].x,
                                                 (unsigned)adjreg[ii].y, 0x5410) * 0x3C00u;
                const unsigned m23 = __byte_perm((unsigned)adjreg[ii].z,
                                                 (unsigned)adjreg[ii].w, 0x5410) * 0x3C00u;
                __half2 p01 = __hmul2(__hmax2(__hmul2(E1r[ii], e2lo), __hmul2(F1r[ii], f2lo)),
                                      *reinterpret_cast<const __half2*>(&m01));
                __half2 p23 = __hmul2(__hmax2(__hmul2(E1r[ii], e2hi), __hmul2(F1r[ii], f2hi)),
                                      *reinterpret_cast<const __half2*>(&m23));
                *reinterpret_cast<uint2*>(&Pn[i * HPH + j4 * 4]) =
                    make_uint2(*reinterpret_cast<unsigned*>(&p01),
                               *reinterpret_cast<unsigned*>(&p23));
            }
            cpa_wait0();
        }
        __syncthreads();
    }

    // write partials (C-frag layout: m16n8 f32)
    const size_t r0 = (size_t)nb + i0 + w * 16 + grp;
    const size_t r1 = r0 + 8;
    #pragma unroll
    for (int ng = 0; ng < 8; ++ng) {
        const int f = ng * 8 + tig * 2;
        float2* d0 = reinterpret_cast<float2*>(&g_acc[js][r0 * FOUT_ + f]);
        float2* d1 = reinterpret_cast<float2*>(&g_acc[js][r1 * FOUT_ + f]);
        *d0 = make_float2(acc[ng][0], acc[ng][1]);
        *d1 = make_float2(acc[ng][2], acc[ng][3]);
    }
    if (tig == 0) {   // ones-column: col 64 holds l
        g_l[js][r0] = acc[8][0];
        g_l[js][r1] = acc[8][2];
    }
}

// ============================================================================
// Kernel 3: combine j-splits, normalize, LayerNorm, ELU.
// ============================================================================
__global__ __launch_bounds__(256) void k3_ln(const float* __restrict__ gamma,
                                             const float* __restrict__ beta,
                                             float* __restrict__ out) {
    const int t = threadIdx.x;
    const int warp = t >> 5, lane = t & 31;
    const int row = blockIdx.x * 8 + warp;
    const size_t base = (size_t)row * FOUT_;

    const float v0 = g_acc[0][base + lane]      + g_acc[1][base + lane];
    const float v1 = g_acc[0][base + 32 + lane] + g_acc[1][base + 32 + lane];
    const float l  = g_l[0][row] + g_l[1][row];
    const float inv = 1.f / l;
    const float h0 = v0 * inv, h1 = v1 * inv;

    float s = h0 + h1;
    #pragma unroll
    for (int o = 16; o; o >>= 1) s += __shfl_xor_sync(0xffffffffu, s, o);
    const float mu = s * (1.f / 64.f);

    const float d0 = h0 - mu, d1 = h1 - mu;
    float vs = d0 * d0 + d1 * d1;
    #pragma unroll
    for (int o = 16; o; o >>= 1) vs += __shfl_xor_sync(0xffffffffu, vs, o);
    const float rstd = rsqrtf(vs * (1.f / 64.f) + 1e-5f);

    const float y0 = d0 * rstd * gamma[lane]      + beta[lane];
    const float y1 = d1 * rstd * gamma[lane + 32] + beta[lane + 32];
    out[base + lane]      = (y0 > 0.f) ? y0 : expm1f(y0);
    out[base + 32 + lane] = (y1 > 0.f) ? y1 : expm1f(y1);
}

// ============================================================================
extern "C" void kernel_launch(void* const* d_in, const int* in_sizes, int n_in,
                              void* d_out, int out_size) {
    const float* x     = (const float*)d_in[0];
    const int*   adj   = (const int*)  d_in[1];
    const float* W     = (const float*)d_in[2];
    const float* a     = (const float*)d_in[3];
    const float* gamma = (const float*)d_in[4];
    const float* beta  = (const float*)d_in[5];
    float* out = (float*)d_out;

    const int smem1 = SM1_FLOATS * (int)sizeof(float);
    const int smem2 = SM2_BYTES;                       // 55296 B
    cudaFuncSetAttribute(k1_proj, cudaFuncAttributeMaxDynamicSharedMemorySize, smem1);
    cudaFuncSetAttribute(k2_attn, cudaFuncAttributeMaxDynamicSharedMemorySize, smem2);

    k1_proj<<<BN_ / 64, 128, smem1>>>(x, W, a);
    k2_attn<<<dim3(N_ / TI, B_, JSPLIT), 256, smem2>>>(adj);
    k3_ln<<<BN_ / 8, 256>>>(gamma, beta, out);
}